// round 11
// baseline (speedup 1.0000x reference)
#include <cuda_runtime.h>
#include <cuda_bf16.h>
#include <math.h>
#include <stdint.h>

#define Bx  32
#define Wt  256
#define IND 4096
#define Hd  1024
#define Zd  100
#define Dd  100
#define G3  3072
#define ZH  1124
#define NHB 128
#define NZB 13
#define HB  (Hd * Bx)
#define NSLOT 16

// ---------------- f32x2 packed-FMA helpers (z-pipeline) ----------------
__device__ __forceinline__ void fma2(unsigned long long& d, unsigned long long a, unsigned long long b) {
    asm("fma.rn.f32x2 %0, %1, %2, %0;" : "+l"(d) : "l"(a), "l"(b));
}
__device__ __forceinline__ float2 unpack2(unsigned long long v) {
    float2 r;
    asm("mov.b64 {%0, %1}, %2;" : "=f"(r.x), "=f"(r.y) : "l"(v));
    return r;
}

// ---------------- L2-coherent load/store + sync primitives ----------------
__device__ __forceinline__ ulonglong2 ldcg_u2(const void* p) {
    ulonglong2 v;
    asm volatile("ld.global.cg.v2.u64 {%0,%1},[%2];" : "=l"(v.x), "=l"(v.y) : "l"(p));
    return v;
}
__device__ __forceinline__ float ldcg_f(const float* p) {
    float v; asm volatile("ld.global.cg.f32 %0,[%1];" : "=f"(v) : "l"(p)); return v;
}
__device__ __forceinline__ uint32_t ldcg_u32(const void* p) {
    uint32_t v; asm volatile("ld.global.cg.b32 %0,[%1];" : "=r"(v) : "l"(p)); return v;
}
__device__ __forceinline__ void stcg_f(float* p, float v) {
    asm volatile("st.global.cg.f32 [%0],%1;" :: "l"(p), "f"(v));
}
__device__ __forceinline__ void stcg_u16(void* p, unsigned short v) {
    asm volatile("st.global.cg.u16 [%0],%1;" :: "l"(p), "h"(v));
}
__device__ __forceinline__ void arrive(unsigned* c) {
    asm volatile("red.release.gpu.global.add.u32 [%0],%1;" :: "l"(c), "r"(1u) : "memory");
}
__device__ __forceinline__ void wait_ge(const unsigned* c, unsigned target) {
    unsigned v;
    do {
        asm volatile("ld.acquire.gpu.global.u32 %0,[%1];" : "=r"(v) : "l"(c) : "memory");
    } while ((int)(v - target) < 0);
}

// ---------------- mma.sync helpers ----------------
__device__ __forceinline__ uint32_t smem_u32(const void* p) {
    uint32_t a;
    asm("{ .reg .u64 t; cvta.to.shared.u64 t, %1; cvt.u32.u64 %0, t; }" : "=r"(a) : "l"(p));
    return a;
}
__device__ __forceinline__ void ldsm4(uint32_t* r, uint32_t addr) {
    asm volatile("ldmatrix.sync.aligned.m8n8.x4.shared.b16 {%0,%1,%2,%3},[%4];"
                 : "=r"(r[0]), "=r"(r[1]), "=r"(r[2]), "=r"(r[3]) : "r"(addr));
}
__device__ __forceinline__ void mma16816(float* c, const uint32_t* a, const uint32_t* b) {
    asm volatile("mma.sync.aligned.m16n8k16.row.col.f32.bf16.bf16.f32 "
                 "{%0,%1,%2,%3},{%4,%5,%6,%7},{%8,%9},{%0,%1,%2,%3};"
                 : "+f"(c[0]), "+f"(c[1]), "+f"(c[2]), "+f"(c[3])
                 : "r"(a[0]), "r"(a[1]), "r"(a[2]), "r"(a[3]), "r"(b[0]), "r"(b[1]));
}
__device__ __forceinline__ void cp_async16(uint32_t saddr, const void* gaddr) {
    asm volatile("cp.async.cg.shared.global [%0],[%1],16;" :: "r"(saddr), "l"(gaddr));
}
#define CP_COMMIT() asm volatile("cp.async.commit_group;" ::: "memory")
#define CP_WAIT(n)  asm volatile("cp.async.wait_group %0;" :: "n"(n) : "memory")

// ---------------- device globals ----------------
__device__ __align__(16) float g_gi [25165824];       // pass0: xh*wh + bias   [W][3H][B]
__device__ __align__(16) float g_giB[25165824];       // pass1: xh*wl
__device__ __align__(16) float g_giC[25165824];       // pass2: xl*wh
__device__ __align__(16) __nv_bfloat16 g_xh[8192 * 4096];
__device__ __align__(16) __nv_bfloat16 g_xl[8192 * 4096];
__device__ __align__(16) __nv_bfloat16 g_wh[3072 * 4096];
__device__ __align__(16) __nv_bfloat16 g_wl[3072 * 4096];
__device__ __align__(16) float g_hring[NSLOT * HB];                   // fp32 h, packed [kq][b][4]
__device__ __align__(16) __nv_bfloat16 g_hb16h[NSLOT][Bx * Hd];       // bf16 hi, [b][k]
__device__ __align__(16) __nv_bfloat16 g_hb16l[NSLOT][Bx * Hd];       // bf16 lo, [b][k]
__device__ __align__(16) float g_zT[Zd * Bx];
__device__ __align__(16) float g_zpreT[Zd * Bx];
__device__ __align__(16) float g_Wmd[Zd * ZH];
__device__ __align__(16) float g_Wsd[Zd * ZH];
__device__ float g_bmu2[Zd];
__device__ float g_bsig2[Zd];
__device__ unsigned g_hprog;
__device__ unsigned g_zaprog;
__device__ unsigned g_zbprog;

// ---------------- prep ----------------
__global__ void prep_kernel(const float* __restrict__ Wd, const float* __restrict__ bd,
                            const float* __restrict__ Wmu, const float* __restrict__ bmu,
                            const float* __restrict__ Wsig, const float* __restrict__ bsig)
{
    int idx = blockIdx.x * blockDim.x + threadIdx.x;
    if (idx < Zd * ZH) {
        int q = idx / ZH, j = idx % ZH;
        float am = 0.f, as = 0.f;
        for (int d = 0; d < Dd; d++) {
            float wd = Wd[(size_t)d * ZH + j];
            am = fmaf(Wmu[q * Dd + d], wd, am);
            as = fmaf(Wsig[q * Dd + d], wd, as);
        }
        g_Wmd[idx] = am;
        g_Wsd[idx] = as;
    }
    if (idx < Zd) {
        float am = bmu[idx], as = bsig[idx];
        for (int d = 0; d < Dd; d++) {
            am = fmaf(Wmu[idx * Dd + d], bd[d], am);
            as = fmaf(Wsig[idx * Dd + d], bd[d], as);
        }
        g_bmu2[idx] = am;
        g_bsig2[idx] = as;
    }
    if (idx < HB) {
        g_hring[idx] = 0.f;
        g_hb16h[0][idx] = __float2bfloat16_rn(0.f);
        g_hb16l[0][idx] = __float2bfloat16_rn(0.f);
    }
    if (idx < Zd * Bx) g_zT[idx] = 0.f;
    if (idx == 0) { g_hprog = 0u; g_zaprog = 0u; g_zbprog = 0u; }
}

// ---------------- split conversions ----------------
__device__ __forceinline__ void split8(const float* s, __nv_bfloat16* h, __nv_bfloat16* l) {
    #pragma unroll
    for (int i = 0; i < 8; i++) {
        float v = s[i];
        __nv_bfloat16 hb = __float2bfloat16_rn(v);
        h[i] = hb;
        l[i] = __float2bfloat16_rn(v - __bfloat162float(hb));
    }
}

__global__ void __launch_bounds__(256) conv_x(const float* __restrict__ x) {
    size_t idx = ((size_t)blockIdx.x * 256 + threadIdx.x) * 8;
    int m = (int)(idx >> 12), k = (int)(idx & 4095);
    int b = m & 31, w = m >> 5;
    float s[8];
    *(float4*)(s)     = *(const float4*)(x + ((size_t)(b * Wt + w) << 12) + k);
    *(float4*)(s + 4) = *(const float4*)(x + ((size_t)(b * Wt + w) << 12) + k + 4);
    __nv_bfloat16 h[8], l[8];
    split8(s, h, l);
    *(uint4*)(g_xh + idx) = *(uint4*)h;
    *(uint4*)(g_xl + idx) = *(uint4*)l;
}

__global__ void __launch_bounds__(256) conv_w(const float* __restrict__ Wih) {
    size_t idx = ((size_t)blockIdx.x * 256 + threadIdx.x) * 8;
    float s[8];
    *(float4*)(s)     = *(const float4*)(Wih + idx);
    *(float4*)(s + 4) = *(const float4*)(Wih + idx + 4);
    __nv_bfloat16 h[8], l[8];
    split8(s, h, l);
    *(uint4*)(g_wh + idx) = *(uint4*)h;
    *(uint4*)(g_wl + idx) = *(uint4*)l;
}

// ---------------- persistent mma.sync GEMM over (tile, pass) work items ----------------
#define NITEM 4608
#define GRID_P 296
#define STG64 32768
#define SMB_B64 16384
#define GEMM_SMEM (3 * STG64)     // 96KB

__global__ void __launch_bounds__(256, 2) gemm_mma(const float* __restrict__ bih) {
    extern __shared__ __align__(128) char smg[];
    const uint32_t sbase = smem_u32(smg);
    const int tid = threadIdx.x;
    const int lane = tid & 31;
    const int wid = tid >> 5;
    const int wm = (wid & 3) * 32;
    const int wn = (wid >> 2) * 64;

    auto sw = [](int r, int cb) -> uint32_t {
        return (uint32_t)(r * 128 + ((cb ^ (r & 7)) << 4));
    };

    uint32_t aoff[2][4], boff[4][4];
    {
        int ml = wm + (lane & 15);
        #pragma unroll
        for (int mt = 0; mt < 2; mt++)
            #pragma unroll
            for (int kh = 0; kh < 4; kh++)
                aoff[mt][kh] = sw(ml + mt * 16, kh * 2 + (lane >> 4));
        int nl = wn + ((lane >> 4) << 3) + (lane & 7);
        #pragma unroll
        for (int p = 0; p < 4; p++)
            #pragma unroll
            for (int kh = 0; kh < 4; kh++)
                boff[p][kh] = (uint32_t)SMB_B64 + sw(nl + p * 16, kh * 2 + ((lane >> 3) & 1));
    }

    #pragma unroll 1
    for (int j = blockIdx.x; j < NITEM; j += GRID_P) {
        const int pass = j / 1536;
        const int rem  = j % 1536;
        const int tm   = rem / 24;
        const int tn   = rem % 24;
        const __nv_bfloat16* Asrc = (pass < 2) ? g_xh : g_xl;
        const __nv_bfloat16* Bsrc = (pass == 1) ? g_wl : g_wh;

        auto load_st = [&](int it, int slot) {
            int k0 = it << 6;
            uint32_t sb = sbase + slot * STG64;
            #pragma unroll
            for (int i = 0; i < 4; i++) {
                int idx = tid + i * 256;
                int r = idx >> 3, cb = idx & 7;
                cp_async16(sb + sw(r, cb), Asrc + (((size_t)(tm * 128 + r)) << 12) + k0 + cb * 8);
            }
            #pragma unroll
            for (int i = 0; i < 4; i++) {
                int idx = tid + i * 256;
                int r = idx >> 3, cb = idx & 7;
                cp_async16(sb + SMB_B64 + sw(r, cb), Bsrc + (((size_t)(tn * 128 + r)) << 12) + k0 + cb * 8);
            }
            CP_COMMIT();
        };

        float acc[2][8][4];
        #pragma unroll
        for (int mt = 0; mt < 2; mt++)
            #pragma unroll
            for (int nt = 0; nt < 8; nt++)
                #pragma unroll
                for (int e = 0; e < 4; e++) acc[mt][nt][e] = 0.f;

        __syncthreads();
        load_st(0, 0);
        load_st(1, 1);

        #pragma unroll 1
        for (int it = 0; it < 64; it++) {
            if (it >= 62) { CP_WAIT(0); } else { CP_WAIT(1); }
            __syncthreads();
            int slot = it % 3;
            uint32_t sb = sbase + slot * STG64;
            #pragma unroll
            for (int kh = 0; kh < 4; kh++) {
                uint32_t a[2][4], b[4][4];
                ldsm4(a[0], sb + aoff[0][kh]);
                ldsm4(a[1], sb + aoff[1][kh]);
                #pragma unroll
                for (int p = 0; p < 4; p++) ldsm4(b[p], sb + boff[p][kh]);
                #pragma unroll
                for (int mt = 0; mt < 2; mt++)
                    #pragma unroll
                    for (int nt = 0; nt < 8; nt++)
                        mma16816(acc[mt][nt], a[mt], &b[nt >> 1][(nt & 1) * 2]);
            }
            if (it + 2 < 64) load_st(it + 2, (it + 2) % 3);
        }

        float* gout = (pass == 0) ? g_gi : ((pass == 1) ? g_giB : g_giC);
        #pragma unroll
        for (int mt = 0; mt < 2; mt++) {
            int row0 = tm * 128 + wm + mt * 16 + (lane >> 2);
            #pragma unroll
            for (int half = 0; half < 2; half++) {
                int row = row0 + half * 8;
                int w = row >> 5, b = row & 31;
                float* orow = gout + (size_t)w * G3 * 32 + b;
                #pragma unroll
                for (int nt = 0; nt < 8; nt++) {
                    int n = tn * 128 + wn + nt * 8 + (lane & 3) * 2;
                    float bia0 = (pass == 0) ? __ldg(bih + n) : 0.f;
                    float bia1 = (pass == 0) ? __ldg(bih + n + 1) : 0.f;
                    orow[(size_t)n * 32]       = acc[mt][nt][half * 2 + 0] + bia0;
                    orow[(size_t)(n + 1) * 32] = acc[mt][nt][half * 2 + 1] + bia1;
                }
            }
        }
    }
}

// ---------------- split-pipeline recurrence ----------------
// h-CTAs (0..127): GRU GEMV via mma.sync — W_hh slice resident in smem as bf16 hi/lo
// swizzled tiles (verified gemm A-path layout); h in bf16 hi/lo ring [b][k], B-frags
// loaded directly from L2 (ld.global.cg.b32 per PTX b-frag spec). 3-pass split, K over warps.
// z-CTAs (128..140): unchanged from R10.
#define A_TILE(ch, hl) (((ch) * 2 + (hl)) * 4096)
#define SRED_OFF 131072
#define SMEM_BYTES (131072 + 8 * 32 * 34 * 4 + 1024)   // A tiles + reduce + pad ≈ 167KB

__global__ void __launch_bounds__(256, 1) recur2(
    const float* __restrict__ Whh, const float* __restrict__ bhh,
    const float* __restrict__ u, const float* __restrict__ Wpnf,
    const float* __restrict__ bpnf, const float* __restrict__ noise,
    float* __restrict__ out)
{
    extern __shared__ __align__(128) char smc[];
    float* sm = (float*)smc;
    const int bk = blockIdx.x;
    const int tid = threadIdx.x;
    const int lane = tid & 31;
    const int wp = tid >> 5;

    float* out_z  = out;
    float* out_mu = out + Bx * Wt * Zd;
    float* out_lv = out + 2 * Bx * Wt * Zd;
    const float u0 = u[0];

    if (bk < NHB) {
        // ================= h-pipeline CTA: mma-based GEMV =================
        const uint32_t sbase = smem_u32(smc);
        float* s_red = (float*)(smc + SRED_OFF);    // [8 w][32 m][34 pad-n]
        const int i0 = bk * 8;

        // --- prologue: W_hh slice -> bf16 hi/lo swizzled tiles (rows m=gate*8+u, pad to 32) ---
        for (int idx = tid; idx < 32 * 1024; idx += 256) {
            int m = idx >> 10, k = idx & 1023;
            float v = 0.f;
            if (m < 24) {
                int g = m >> 3, uu = m & 7;
                v = Whh[(size_t)(g * Hd + i0 + uu) * Hd + k];
            }
            __nv_bfloat16 hi = __float2bfloat16_rn(v);
            __nv_bfloat16 lo = __float2bfloat16_rn(v - __bfloat162float(hi));
            int ch = k >> 6, kp = k & 63, cb = kp >> 3, e = kp & 7;
            uint32_t off = (uint32_t)(m * 128 + ((cb ^ (m & 7)) << 4) + e * 2);
            *(__nv_bfloat16*)(smc + A_TILE(ch, 0) + off) = hi;
            *(__nv_bfloat16*)(smc + A_TILE(ch, 1) + off) = lo;
        }
        __syncthreads();

        const int i = i0 + wp;                 // finalize thread (u=wp, b=lane)
        const float bhr = bhh[i];
        const float bhz = bhh[Hd + i];
        const float bhn = bhh[2 * Hd + i];
        const int hoff = ((i >> 2) * 32 + lane) * 4 + (i & 3);

        // ldsm A offsets (within a 32x64 tile), kh = 0..3
        uint32_t aoff[2][4];
        #pragma unroll
        for (int mt = 0; mt < 2; mt++)
            #pragma unroll
            for (int kh = 0; kh < 4; kh++) {
                int r = (lane & 15) + mt * 16;
                int cb = kh * 2 + (lane >> 4);
                aoff[mt][kh] = (uint32_t)(r * 128 + ((cb ^ (r & 7)) << 4));
            }

        // B fragment addressing: [b][k] bf16, lane -> (b = nt*8 + (lane>>2), k = k0 + 2(lane&3))
        const int brow = lane >> 2;
        const int bkof = 2 * (lane & 3);

        #pragma unroll 1
        for (int t = 0; t < Wt; t++) {
            if (tid == 0) {
                if (t > 0) wait_ge(&g_hprog, (unsigned)(NHB * t));
                if (t >= NSLOT) wait_ge(&g_zaprog, (unsigned)(NZB * (t - (NSLOT - 1))));
            }
            __syncthreads();

            const size_t gbase = ((size_t)t * G3) * 32;
            size_t o_r = gbase + (size_t)(0 * Hd + i) * 32 + lane;
            size_t o_z = gbase + (size_t)(1 * Hd + i) * 32 + lane;
            size_t o_n = gbase + (size_t)(2 * Hd + i) * 32 + lane;
            float gir = g_gi[o_r] + g_giB[o_r] + g_giC[o_r];
            float giz = g_gi[o_z] + g_giB[o_z] + g_giC[o_z];
            float gin = g_gi[o_n] + g_giB[o_n] + g_giC[o_n];
            float hold = ldcg_f(g_hring + (size_t)(t & (NSLOT - 1)) * HB + hoff);

            const char* Hh = (const char*)g_hb16h[t & (NSLOT - 1)];
            const char* Hl = (const char*)g_hb16l[t & (NSLOT - 1)];

            float acc[2][4][4];
            #pragma unroll
            for (int mt = 0; mt < 2; mt++)
                #pragma unroll
                for (int nt = 0; nt < 4; nt++)
                    #pragma unroll
                    for (int e = 0; e < 4; e++) acc[mt][nt][e] = 0.f;

            uint32_t bh[4][2], bl[4][2], bhn2[4][2], bln2[4][2];
            auto loadB = [&](int k0, uint32_t bh_[4][2], uint32_t bl_[4][2]) {
                #pragma unroll
                for (int nt = 0; nt < 4; nt++) {
                    size_t byt = ((size_t)((nt * 8 + brow) << 10) + k0 + bkof) * 2;
                    bh_[nt][0] = ldcg_u32(Hh + byt);
                    bh_[nt][1] = ldcg_u32(Hh + byt + 16);
                    bl_[nt][0] = ldcg_u32(Hl + byt);
                    bl_[nt][1] = ldcg_u32(Hl + byt + 16);
                }
            };

            loadB((2 * wp) * 64, bh, bl);     // kk = 0
            #pragma unroll
            for (int kk = 0; kk < 8; kk++) {
                int ch = 2 * wp + (kk >> 2);
                int kh = kk & 3;
                uint32_t a_hi[2][4], a_lo[2][4];
                #pragma unroll
                for (int mt = 0; mt < 2; mt++) {
                    ldsm4(a_hi[mt], sbase + A_TILE(ch, 0) + aoff[mt][kh]);
                    ldsm4(a_lo[mt], sbase + A_TILE(ch, 1) + aoff[mt][kh]);
                }
                if (kk < 7) {
                    int kk2 = kk + 1;
                    loadB((2 * wp + (kk2 >> 2)) * 64 + (kk2 & 3) * 16, bhn2, bln2);
                }
                #pragma unroll
                for (int mt = 0; mt < 2; mt++)
                    #pragma unroll
                    for (int nt = 0; nt < 4; nt++) {
                        mma16816(acc[mt][nt], a_hi[mt], bh[nt]);
                        mma16816(acc[mt][nt], a_hi[mt], bl[nt]);
                        mma16816(acc[mt][nt], a_lo[mt], bh[nt]);
                    }
                if (kk < 7) {
                    #pragma unroll
                    for (int nt = 0; nt < 4; nt++) {
                        bh[nt][0] = bhn2[nt][0]; bh[nt][1] = bhn2[nt][1];
                        bl[nt][0] = bln2[nt][0]; bl[nt][1] = bln2[nt][1];
                    }
                }
            }

            // write per-warp partials: C[m][n], m = mt*16 + (lane>>2) + 8h, n = nt*8 + 2(lane&3)+e
            #pragma unroll
            for (int mt = 0; mt < 2; mt++)
                #pragma unroll
                for (int nt = 0; nt < 4; nt++)
                    #pragma unroll
                    for (int h2 = 0; h2 < 2; h2++) {
                        int m = mt * 16 + (lane >> 2) + h2 * 8;
                        int n = nt * 8 + 2 * (lane & 3);
                        float2 v2 = make_float2(acc[mt][nt][h2 * 2 + 0], acc[mt][nt][h2 * 2 + 1]);
                        *(float2*)&s_red[(wp * 32 + m) * 34 + n] = v2;
                    }
            __syncthreads();

            // reduce over 8 warps: thread (u=wp, b=lane); gates at m = g*8+u
            float ar = 0.f, az = 0.f, an = 0.f;
            #pragma unroll
            for (int w2 = 0; w2 < 8; w2++) {
                ar += s_red[(w2 * 32 + wp     ) * 34 + lane];
                az += s_red[(w2 * 32 + 8 + wp ) * 34 + lane];
                an += s_red[(w2 * 32 + 16 + wp) * 34 + lane];
            }
            float rg = 1.f / (1.f + expf(-(gir + ar + bhr)));
            float zg = 1.f / (1.f + expf(-(giz + az + bhz)));
            float ng = tanhf(gin + rg * (an + bhn));
            float hnew = (1.f - zg) * ng + zg * hold;

            int ns = (t + 1) & (NSLOT - 1);
            stcg_f(g_hring + (size_t)ns * HB + hoff, hnew);
            __nv_bfloat16 hi16 = __float2bfloat16_rn(hnew);
            __nv_bfloat16 lo16 = __float2bfloat16_rn(hnew - __bfloat162float(hi16));
            stcg_u16(&g_hb16h[ns][lane * Hd + i], *(unsigned short*)&hi16);
            stcg_u16(&g_hb16l[ns][lane * Hd + i], *(unsigned short*)&lo16);

            __syncthreads();
            if (tid == 0) arrive(&g_hprog);
        }
    } else {
        // ---------------- z-pipeline CTA (unchanged from R10) ----------------
        const int zb = bk - NHB;
        const int q0 = zb * 8;
        float* s_wz  = sm;
        float* s_wzz = sm + 16384;
        float* s_pnf = sm + 16384 + 1600;
        float* s_red = sm + 16384 + 1600 + 832;

        for (int idx = tid; idx < 8 * ZH; idx += 256) {
            int q8 = idx / ZH, jj = idx % ZH;
            int q = q0 + q8;
            float wm = (q < Zd) ? g_Wmd[(size_t)q * ZH + jj] : 0.f;
            float ws = (q < Zd) ? g_Wsd[(size_t)q * ZH + jj] : 0.f;
            if (jj < Zd) {
                s_wzz[jj * 16 + q8 * 2 + 0] = wm;
                s_wzz[jj * 16 + q8 * 2 + 1] = ws;
            } else {
                int kk = jj - Zd;
                int kq = kk >> 2, c = kk & 3;
                s_wz[(kq * 16 + q8 * 2 + 0) * 4 + c] = wm;
                s_wz[(kq * 16 + q8 * 2 + 1) * 4 + c] = ws;
            }
        }
        for (int idx = tid; idx < 8 * Zd; idx += 256) {
            int q8 = idx / Zd, z2 = idx % Zd;
            int q = q0 + q8;
            s_pnf[q8 * 104 + z2] = (q < Zd) ? Wpnf[q * Zd + z2] : 0.f;
        }
        __syncthreads();

        const int q = q0 + wp;
        const bool qa = (q < Zd);
        const float bm2 = qa ? g_bmu2[q] : 0.f;
        const float bs2 = qa ? g_bsig2[q] : 0.f;
        const float bpq = qa ? bpnf[q] : 0.f;
        const int kq0 = wp * 32;

        #pragma unroll 1
        for (int t = 0; t < Wt; t++) {
            if (tid == 0) {
                wait_ge(&g_hprog, (unsigned)(NHB * (t + 1)));
                if (t > 0) wait_ge(&g_zbprog, (unsigned)(NZB * t));
            }
            __syncthreads();

            float zacc[16];
            #pragma unroll
            for (int ug = 0; ug < 16; ug++) zacc[ug] = 0.f;
            for (int z2 = wp; z2 < Zd; z2 += 8) {
                float zv = ldcg_f(g_zT + z2 * 32 + lane);
                #pragma unroll
                for (int ug = 0; ug < 16; ug++)
                    zacc[ug] = fmaf(zv, s_wzz[z2 * 16 + ug], zacc[ug]);
            }

            const float* hb = g_hring + (size_t)((t + 1) & (NSLOT - 1)) * HB;
            unsigned long long acc[16];
            #pragma unroll
            for (int ug = 0; ug < 16; ug++) acc[ug] = 0ull;

            #pragma unroll 1
            for (int jb = 0; jb < 32; jb += 8) {
                ulonglong2 hv[8];
                #pragma unroll
                for (int j = 0; j < 8; j++)
                    hv[j] = ldcg_u2(hb + (size_t)((kq0 + jb + j) * 32 + lane) * 4);
                #pragma unroll
                for (int j = 0; j < 8; j++) {
                    const ulonglong2* wq = (const ulonglong2*)(s_wz + (size_t)(kq0 + jb + j) * 64);
                    #pragma unroll
                    for (int ug = 0; ug < 16; ug++) {
                        ulonglong2 w2 = wq[ug];
                        fma2(acc[ug], hv[j].x, w2.x);
                        fma2(acc[ug], hv[j].y, w2.y);
                    }
                }
            }
            #pragma unroll
            for (int ug = 0; ug < 16; ug++) {
                float2 p = unpack2(acc[ug]);
                s_red[(wp * 16 + ug) * 32 + lane] = zacc[ug] + p.x + p.y;
            }
            __syncthreads();

            float zp = 0.f;
            if (qa) {
                float m = bm2, s = bs2;
                #pragma unroll
                for (int ww = 0; ww < 8; ww++) {
                    m += s_red[(ww * 16 + wp * 2 + 0) * 32 + lane];
                    s += s_red[(ww * 16 + wp * 2 + 1) * 32 + lane];
                }
                float lv = fmaxf(s, 0.f) + log1pf(expf(-fabsf(s)));
                float eps = noise[(size_t)(t * Bx + lane) * Zd + q];
                zp = m + expf(0.5f * lv) * eps;
                stcg_f(g_zpreT + q * 32 + lane, zp);
                out_mu[(size_t)(lane * Wt + t) * Zd + q] = m;
                out_lv[(size_t)(lane * Wt + t) * Zd + q] = lv;
            }
            __syncthreads();
            if (tid == 0) {
                arrive(&g_zaprog);
                wait_ge(&g_zaprog, (unsigned)(NZB * (t + 1)));
            }
            __syncthreads();

            if (qa) {
                const float* pnf = s_pnf + wp * 104;
                float a0 = 0.f, a1 = 0.f;
                #pragma unroll 4
                for (int z2 = 0; z2 < Zd; z2 += 2) {
                    a0 = fmaf(ldcg_f(g_zpreT + (z2 + 0) * 32 + lane), pnf[z2 + 0], a0);
                    a1 = fmaf(ldcg_f(g_zpreT + (z2 + 1) * 32 + lane), pnf[z2 + 1], a1);
                }
                float zn = zp + u0 * tanhf((a0 + a1) + bpq);
                out_z[(size_t)(lane * Wt + t) * Zd + q] = zn;
                stcg_f(g_zT + q * 32 + lane, zn);
            }
            __syncthreads();
            if (tid == 0) arrive(&g_zbprog);
        }
    }
}

// ---------------- launch ----------------
extern "C" void kernel_launch(void* const* d_in, const int* in_sizes, int n_in,
                              void* d_out, int out_size)
{
    const float* x    = (const float*)d_in[0];
    const float* Wih  = (const float*)d_in[1];
    const float* Whh  = (const float*)d_in[2];
    const float* bih  = (const float*)d_in[3];
    const float* bhh  = (const float*)d_in[4];
    const float* Wd   = (const float*)d_in[5];
    const float* bd   = (const float*)d_in[6];
    const float* Wmu  = (const float*)d_in[7];
    const float* bmu  = (const float*)d_in[8];
    const float* Wsig = (const float*)d_in[9];
    const float* bsig = (const float*)d_in[10];
    const float* u    = (const float*)d_in[11];
    const float* Wpnf = (const float*)d_in[12];
    const float* bpnf = (const float*)d_in[13];
    const float* noise= (const float*)d_in[14];
    float* out = (float*)d_out;

    cudaFuncSetAttribute(recur2, cudaFuncAttributeMaxDynamicSharedMemorySize, SMEM_BYTES);
    cudaFuncSetAttribute(gemm_mma, cudaFuncAttributeMaxDynamicSharedMemorySize, GEMM_SMEM);

    prep_kernel<<<(Zd * ZH + 255) / 256, 256>>>(Wd, bd, Wmu, bmu, Wsig, bsig);
    conv_x<<<(8192 * 4096) / (8 * 256), 256>>>(x);
    conv_w<<<(3072 * 4096) / (8 * 256), 256>>>(Wih);
    gemm_mma<<<GRID_P, 256, GEMM_SMEM>>>(bih);
    recur2<<<NHB + NZB, 256, SMEM_BYTES>>>(Whh, bhh, u, Wpnf, bpnf, noise, out);
}

// round 12
// speedup vs baseline: 1.2463x; 1.2463x over previous
#include <cuda_runtime.h>
#include <cuda_bf16.h>
#include <math.h>
#include <stdint.h>

#define Bx  32
#define Wt  256
#define IND 4096
#define Hd  1024
#define Zd  100
#define Dd  100
#define G3  3072
#define ZH  1124
#define NHB 128
#define NZB 13
#define NGW 155                      // gemm worker CTAs
#define NCTA (NHB + NZB + NGW)       // 296
#define HB  (Hd * Bx)
#define NSLOT 16

// ---------------- f32x2 packed-FMA helpers ----------------
__device__ __forceinline__ void fma2(unsigned long long& d, unsigned long long a, unsigned long long b) {
    asm("fma.rn.f32x2 %0, %1, %2, %0;" : "+l"(d) : "l"(a), "l"(b));
}
__device__ __forceinline__ float2 unpack2(unsigned long long v) {
    float2 r;
    asm("mov.b64 {%0, %1}, %2;" : "=f"(r.x), "=f"(r.y) : "l"(v));
    return r;
}

// ---------------- L2-coherent load/store + sync primitives ----------------
__device__ __forceinline__ ulonglong2 ldcg_u2(const void* p) {
    ulonglong2 v;
    asm volatile("ld.global.cg.v2.u64 {%0,%1},[%2];" : "=l"(v.x), "=l"(v.y) : "l"(p));
    return v;
}
__device__ __forceinline__ float ldcg_f(const float* p) {
    float v; asm volatile("ld.global.cg.f32 %0,[%1];" : "=f"(v) : "l"(p)); return v;
}
__device__ __forceinline__ void stcg_f(float* p, float v) {
    asm volatile("st.global.cg.f32 [%0],%1;" :: "l"(p), "f"(v));
}
__device__ __forceinline__ void arrive(unsigned* c) {
    asm volatile("red.release.gpu.global.add.u32 [%0],%1;" :: "l"(c), "r"(1u) : "memory");
}
__device__ __forceinline__ void wait_ge(const unsigned* c, unsigned target) {
    unsigned v;
    do {
        asm volatile("ld.acquire.gpu.global.u32 %0,[%1];" : "=r"(v) : "l"(c) : "memory");
    } while ((int)(v - target) < 0);
}

// ---------------- mma.sync helpers ----------------
__device__ __forceinline__ uint32_t smem_u32(const void* p) {
    uint32_t a;
    asm("{ .reg .u64 t; cvta.to.shared.u64 t, %1; cvt.u32.u64 %0, t; }" : "=r"(a) : "l"(p));
    return a;
}
__device__ __forceinline__ void ldsm4(uint32_t* r, uint32_t addr) {
    asm volatile("ldmatrix.sync.aligned.m8n8.x4.shared.b16 {%0,%1,%2,%3},[%4];"
                 : "=r"(r[0]), "=r"(r[1]), "=r"(r[2]), "=r"(r[3]) : "r"(addr));
}
__device__ __forceinline__ void mma16816(float* c, const uint32_t* a, const uint32_t* b) {
    asm volatile("mma.sync.aligned.m16n8k16.row.col.f32.bf16.bf16.f32 "
                 "{%0,%1,%2,%3},{%4,%5,%6,%7},{%8,%9},{%0,%1,%2,%3};"
                 : "+f"(c[0]), "+f"(c[1]), "+f"(c[2]), "+f"(c[3])
                 : "r"(a[0]), "r"(a[1]), "r"(a[2]), "r"(a[3]), "r"(b[0]), "r"(b[1]));
}
__device__ __forceinline__ void cp_async16(uint32_t saddr, const void* gaddr) {
    asm volatile("cp.async.cg.shared.global [%0],[%1],16;" :: "r"(saddr), "l"(gaddr));
}
#define CP_COMMIT() asm volatile("cp.async.commit_group;" ::: "memory")
#define CP_WAIT(n)  asm volatile("cp.async.wait_group %0;" :: "n"(n) : "memory")

// ---------------- device globals ----------------
__device__ __align__(16) float g_gi [25165824];       // pass0: xh*wh + bias   [W][3H][B]
__device__ __align__(16) float g_giB[25165824];       // pass1: xh*wl
__device__ __align__(16) float g_giC[25165824];       // pass2: xl*wh
__device__ __align__(16) __nv_bfloat16 g_xh[8192 * 4096];
__device__ __align__(16) __nv_bfloat16 g_xl[8192 * 4096];
__device__ __align__(16) __nv_bfloat16 g_wh[3072 * 4096];
__device__ __align__(16) __nv_bfloat16 g_wl[3072 * 4096];
__device__ __align__(16) float g_hring[NSLOT * HB];
__device__ __align__(16) float g_zT[Zd * Bx];
__device__ __align__(16) float g_zpreT[Zd * Bx];
__device__ __align__(16) float g_Wmd[Zd * ZH];
__device__ __align__(16) float g_Wsd[Zd * ZH];
__device__ float g_bmu2[Zd];
__device__ float g_bsig2[Zd];
__device__ unsigned g_hprog;
__device__ unsigned g_zaprog;
__device__ unsigned g_zbprog;
__device__ unsigned g_item;          // gemm work queue
__device__ unsigned g_tmdone[64];    // per-tm completed item count (72 = done)

// ---------------- prep ----------------
__global__ void prep_kernel(const float* __restrict__ Wd, const float* __restrict__ bd,
                            const float* __restrict__ Wmu, const float* __restrict__ bmu,
                            const float* __restrict__ Wsig, const float* __restrict__ bsig)
{
    int idx = blockIdx.x * blockDim.x + threadIdx.x;
    if (idx < Zd * ZH) {
        int q = idx / ZH, j = idx % ZH;
        float am = 0.f, as = 0.f;
        for (int d = 0; d < Dd; d++) {
            float wd = Wd[(size_t)d * ZH + j];
            am = fmaf(Wmu[q * Dd + d], wd, am);
            as = fmaf(Wsig[q * Dd + d], wd, as);
        }
        g_Wmd[idx] = am;
        g_Wsd[idx] = as;
    }
    if (idx < Zd) {
        float am = bmu[idx], as = bsig[idx];
        for (int d = 0; d < Dd; d++) {
            am = fmaf(Wmu[idx * Dd + d], bd[d], am);
            as = fmaf(Wsig[idx * Dd + d], bd[d], as);
        }
        g_bmu2[idx] = am;
        g_bsig2[idx] = as;
    }
    if (idx < HB) g_hring[idx] = 0.f;
    if (idx < Zd * Bx) g_zT[idx] = 0.f;
    if (idx < 64) g_tmdone[idx] = 0u;
    if (idx == 0) { g_hprog = 0u; g_zaprog = 0u; g_zbprog = 0u; g_item = 0u; }
}

// ---------------- split conversions ----------------
__device__ __forceinline__ void split8(const float* s, __nv_bfloat16* h, __nv_bfloat16* l) {
    #pragma unroll
    for (int i = 0; i < 8; i++) {
        float v = s[i];
        __nv_bfloat16 hb = __float2bfloat16_rn(v);
        h[i] = hb;
        l[i] = __float2bfloat16_rn(v - __bfloat162float(hb));
    }
}

__global__ void __launch_bounds__(256) conv_x(const float* __restrict__ x) {
    size_t idx = ((size_t)blockIdx.x * 256 + threadIdx.x) * 8;
    int m = (int)(idx >> 12), k = (int)(idx & 4095);
    int b = m & 31, w = m >> 5;
    float s[8];
    *(float4*)(s)     = *(const float4*)(x + ((size_t)(b * Wt + w) << 12) + k);
    *(float4*)(s + 4) = *(const float4*)(x + ((size_t)(b * Wt + w) << 12) + k + 4);
    __nv_bfloat16 h[8], l[8];
    split8(s, h, l);
    *(uint4*)(g_xh + idx) = *(uint4*)h;
    *(uint4*)(g_xl + idx) = *(uint4*)l;
}

__global__ void __launch_bounds__(256) conv_w(const float* __restrict__ Wih) {
    size_t idx = ((size_t)blockIdx.x * 256 + threadIdx.x) * 8;
    float s[8];
    *(float4*)(s)     = *(const float4*)(Wih + idx);
    *(float4*)(s + 4) = *(const float4*)(Wih + idx + 4);
    __nv_bfloat16 h[8], l[8];
    split8(s, h, l);
    *(uint4*)(g_wh + idx) = *(uint4*)h;
    *(uint4*)(g_wl + idx) = *(uint4*)l;
}

// ---------------- mega kernel: 128 h-CTAs + 13 z-CTAs + 155 gemm workers ----------------
#define NITEM 4608
#define STG64 32768
#define SMB_B64 16384
#define MEGA_SMEM (110 * 1024)       // 110KB -> 2 CTAs/SM

__global__ void __launch_bounds__(256, 2) mega(
    const float* __restrict__ Whh, const float* __restrict__ bhh,
    const float* __restrict__ u, const float* __restrict__ Wpnf,
    const float* __restrict__ bpnf, const float* __restrict__ noise,
    const float* __restrict__ bih, float* __restrict__ out)
{
    extern __shared__ __align__(128) char smc[];
    float* sm = (float*)smc;
    const int bk = blockIdx.x;
    const int tid = threadIdx.x;
    const int lane = tid & 31;
    const int wp = tid >> 5;

    float* out_z  = out;
    float* out_mu = out + Bx * Wt * Zd;
    float* out_lv = out + 2 * Bx * Wt * Zd;

    if (bk >= NHB + NZB) {
        // ================= gemm worker CTA =================
        const uint32_t sbase = smem_u32(smc);
        const int wm = (wp & 3) * 32;
        const int wn = (wp >> 2) * 64;

        auto sw = [](int r, int cb) -> uint32_t {
            return (uint32_t)(r * 128 + ((cb ^ (r & 7)) << 4));
        };
        uint32_t aoff[2][4], boff[4][4];
        {
            int ml = wm + (lane & 15);
            #pragma unroll
            for (int mt = 0; mt < 2; mt++)
                #pragma unroll
                for (int kh = 0; kh < 4; kh++)
                    aoff[mt][kh] = sw(ml + mt * 16, kh * 2 + (lane >> 4));
            int nl = wn + ((lane >> 4) << 3) + (lane & 7);
            #pragma unroll
            for (int p = 0; p < 4; p++)
                #pragma unroll
                for (int kh = 0; kh < 4; kh++)
                    boff[p][kh] = (uint32_t)SMB_B64 + sw(nl + p * 16, kh * 2 + ((lane >> 3) & 1));
        }

        __shared__ unsigned s_item;
        for (;;) {
            __syncthreads();                 // protect smem slots + s_item from prev item
            if (tid == 0) s_item = atomicAdd(&g_item, 1u);
            __syncthreads();
            unsigned j = s_item;
            if (j >= NITEM) break;
            // tm-major item order: tm = j/72; within: pass = rem/24, tn = rem%24
            const int tm   = j / 72;
            const int rem  = j % 72;
            const int pass = rem / 24;
            const int tn   = rem % 24;
            const __nv_bfloat16* Asrc = (pass < 2) ? g_xh : g_xl;
            const __nv_bfloat16* Bsrc = (pass == 1) ? g_wl : g_wh;

            auto load_st = [&](int it, int slot) {
                int k0 = it << 6;
                uint32_t sb = sbase + slot * STG64;
                #pragma unroll
                for (int i = 0; i < 4; i++) {
                    int idx = tid + i * 256;
                    int r = idx >> 3, cb = idx & 7;
                    cp_async16(sb + sw(r, cb), Asrc + (((size_t)(tm * 128 + r)) << 12) + k0 + cb * 8);
                }
                #pragma unroll
                for (int i = 0; i < 4; i++) {
                    int idx = tid + i * 256;
                    int r = idx >> 3, cb = idx & 7;
                    cp_async16(sb + SMB_B64 + sw(r, cb), Bsrc + (((size_t)(tn * 128 + r)) << 12) + k0 + cb * 8);
                }
                CP_COMMIT();
            };

            float acc[2][8][4];
            #pragma unroll
            for (int mt = 0; mt < 2; mt++)
                #pragma unroll
                for (int nt = 0; nt < 8; nt++)
                    #pragma unroll
                    for (int e = 0; e < 4; e++) acc[mt][nt][e] = 0.f;

            load_st(0, 0);
            load_st(1, 1);

            #pragma unroll 1
            for (int it = 0; it < 64; it++) {
                if (it >= 62) { CP_WAIT(0); } else { CP_WAIT(1); }
                __syncthreads();
                int slot = it % 3;
                uint32_t sb = sbase + slot * STG64;
                #pragma unroll
                for (int kh = 0; kh < 4; kh++) {
                    uint32_t a[2][4], b[4][4];
                    ldsm4(a[0], sb + aoff[0][kh]);
                    ldsm4(a[1], sb + aoff[1][kh]);
                    #pragma unroll
                    for (int p = 0; p < 4; p++) ldsm4(b[p], sb + boff[p][kh]);
                    #pragma unroll
                    for (int mt = 0; mt < 2; mt++)
                        #pragma unroll
                        for (int nt = 0; nt < 8; nt++)
                            mma16816(acc[mt][nt], a[mt], &b[nt >> 1][(nt & 1) * 2]);
                }
                if (it + 2 < 64) load_st(it + 2, (it + 2) % 3);
            }

            float* gout = (pass == 0) ? g_gi : ((pass == 1) ? g_giB : g_giC);
            #pragma unroll
            for (int mt = 0; mt < 2; mt++) {
                int row0 = tm * 128 + wm + mt * 16 + (lane >> 2);
                #pragma unroll
                for (int half = 0; half < 2; half++) {
                    int row = row0 + half * 8;
                    int w = row >> 5, b = row & 31;
                    float* orow = gout + (size_t)w * G3 * 32 + b;
                    #pragma unroll
                    for (int nt = 0; nt < 8; nt++) {
                        int n = tn * 128 + wn + nt * 8 + (lane & 3) * 2;
                        float bia0 = (pass == 0) ? __ldg(bih + n) : 0.f;
                        float bia1 = (pass == 0) ? __ldg(bih + n + 1) : 0.f;
                        orow[(size_t)n * 32]       = acc[mt][nt][half * 2 + 0] + bia0;
                        orow[(size_t)(n + 1) * 32] = acc[mt][nt][half * 2 + 1] + bia1;
                    }
                }
            }
            __syncthreads();                 // all stores done (CTA-wide) before signal
            if (tid == 0) arrive(&g_tmdone[tm]);
        }
    } else if (bk < NHB) {
        // ================= h-pipeline CTA (R10 logic; 12KB two-phase reduce; gi gating) =================
        float* s_whh = sm;                   // 24*1024 floats = 96KB
        float* s_red = sm + 24 * 1024;       // [4][24][32] = 12KB
        const int i0 = bk * 8;

        for (int idx = tid; idx < 24576; idx += 256) {
            int c = idx & 3;
            int rest = idx >> 2;
            int g = rest % 3;
            int t2 = rest / 3;
            int uu = t2 & 7;
            int kq = t2 >> 3;
            s_whh[idx] = Whh[(size_t)(g * Hd + i0 + uu) * Hd + kq * 4 + c];
        }
        __syncthreads();

        const int i = i0 + wp;
        const float bhr = bhh[i];
        const float bhz = bhh[Hd + i];
        const float bhn = bhh[2 * Hd + i];
        const int hoff = ((i >> 2) * 32 + lane) * 4 + (i & 3);
        const int kq0 = wp * 32;

        #pragma unroll 1
        for (int t = 0; t < Wt; t++) {
            if (tid == 0) {
                wait_ge(&g_tmdone[t >> 2], 72u);          // gi tiles for step t ready
                if (t > 0) wait_ge(&g_hprog, (unsigned)(NHB * t));
                if (t >= NSLOT) wait_ge(&g_zaprog, (unsigned)(NZB * (t - (NSLOT - 1))));
            }
            __syncthreads();

            const size_t gbase = ((size_t)t * G3) * 32;
            size_t o_r = gbase + (size_t)(0 * Hd + i) * 32 + lane;
            size_t o_z = gbase + (size_t)(1 * Hd + i) * 32 + lane;
            size_t o_n = gbase + (size_t)(2 * Hd + i) * 32 + lane;
            float gir = g_gi[o_r] + g_giB[o_r] + g_giC[o_r];
            float giz = g_gi[o_z] + g_giB[o_z] + g_giC[o_z];
            float gin = g_gi[o_n] + g_giB[o_n] + g_giC[o_n];
            const float* hb = g_hring + (size_t)(t & (NSLOT - 1)) * HB;
            float hold = ldcg_f(hb + hoff);

            unsigned long long acc[24];
            #pragma unroll
            for (int ug = 0; ug < 24; ug++) acc[ug] = 0ull;

            #pragma unroll 1
            for (int jb = 0; jb < 32; jb += 8) {
                ulonglong2 hv[8];
                #pragma unroll
                for (int j = 0; j < 8; j++)
                    hv[j] = ldcg_u2(hb + (size_t)((kq0 + jb + j) * 32 + lane) * 4);
                #pragma unroll
                for (int j = 0; j < 8; j++) {
                    const ulonglong2* wq = (const ulonglong2*)(s_whh + (size_t)(kq0 + jb + j) * 96);
                    #pragma unroll
                    for (int ug = 0; ug < 24; ug++) {
                        ulonglong2 w2 = wq[ug];
                        fma2(acc[ug], hv[j].x, w2.x);
                        fma2(acc[ug], hv[j].y, w2.y);
                    }
                }
            }
            float part[24];
            #pragma unroll
            for (int ug = 0; ug < 24; ug++) {
                float2 p = unpack2(acc[ug]);
                part[ug] = p.x + p.y;
            }
            // two-phase reduce into [4][24][32]
            if (wp >= 4) {
                #pragma unroll
                for (int ug = 0; ug < 24; ug++)
                    s_red[((wp - 4) * 24 + ug) * 32 + lane] = part[ug];
            }
            __syncthreads();
            if (wp < 4) {
                #pragma unroll
                for (int ug = 0; ug < 24; ug++)
                    s_red[(wp * 24 + ug) * 32 + lane] += part[ug];
            }
            __syncthreads();

            float ar = 0.f, az = 0.f, an = 0.f;
            #pragma unroll
            for (int w2 = 0; w2 < 4; w2++) {
                ar += s_red[(w2 * 24 + wp * 3 + 0) * 32 + lane];
                az += s_red[(w2 * 24 + wp * 3 + 1) * 32 + lane];
                an += s_red[(w2 * 24 + wp * 3 + 2) * 32 + lane];
            }
            float rg = 1.f / (1.f + expf(-(gir + ar + bhr)));
            float zg = 1.f / (1.f + expf(-(giz + az + bhz)));
            float ng = tanhf(gin + rg * (an + bhn));
            float hnew = (1.f - zg) * ng + zg * hold;
            stcg_f(g_hring + (size_t)((t + 1) & (NSLOT - 1)) * HB + hoff, hnew);

            __syncthreads();
            if (tid == 0) arrive(&g_hprog);
        }
    } else {
        // ================= z-pipeline CTA (R10 unchanged) =================
        const float u0 = u[0];
        const int zb = bk - NHB;
        const int q0 = zb * 8;
        float* s_wz  = sm;
        float* s_wzz = sm + 16384;
        float* s_pnf = sm + 16384 + 1600;
        float* s_red = sm + 16384 + 1600 + 832;

        for (int idx = tid; idx < 8 * ZH; idx += 256) {
            int q8 = idx / ZH, jj = idx % ZH;
            int q = q0 + q8;
            float wm = (q < Zd) ? g_Wmd[(size_t)q * ZH + jj] : 0.f;
            float ws = (q < Zd) ? g_Wsd[(size_t)q * ZH + jj] : 0.f;
            if (jj < Zd) {
                s_wzz[jj * 16 + q8 * 2 + 0] = wm;
                s_wzz[jj * 16 + q8 * 2 + 1] = ws;
            } else {
                int kk = jj - Zd;
                int kq = kk >> 2, c = kk & 3;
                s_wz[(kq * 16 + q8 * 2 + 0) * 4 + c] = wm;
                s_wz[(kq * 16 + q8 * 2 + 1) * 4 + c] = ws;
            }
        }
        for (int idx = tid; idx < 8 * Zd; idx += 256) {
            int q8 = idx / Zd, z2 = idx % Zd;
            int q = q0 + q8;
            s_pnf[q8 * 104 + z2] = (q < Zd) ? Wpnf[q * Zd + z2] : 0.f;
        }
        __syncthreads();

        const int q = q0 + wp;
        const bool qa = (q < Zd);
        const float bm2 = qa ? g_bmu2[q] : 0.f;
        const float bs2 = qa ? g_bsig2[q] : 0.f;
        const float bpq = qa ? bpnf[q] : 0.f;
        const int kq0 = wp * 32;

        #pragma unroll 1
        for (int t = 0; t < Wt; t++) {
            if (tid == 0) {
                wait_ge(&g_hprog, (unsigned)(NHB * (t + 1)));
                if (t > 0) wait_ge(&g_zbprog, (unsigned)(NZB * t));
            }
            __syncthreads();

            float zacc[16];
            #pragma unroll
            for (int ug = 0; ug < 16; ug++) zacc[ug] = 0.f;
            for (int z2 = wp; z2 < Zd; z2 += 8) {
                float zv = ldcg_f(g_zT + z2 * 32 + lane);
                #pragma unroll
                for (int ug = 0; ug < 16; ug++)
                    zacc[ug] = fmaf(zv, s_wzz[z2 * 16 + ug], zacc[ug]);
            }

            const float* hb = g_hring + (size_t)((t + 1) & (NSLOT - 1)) * HB;
            unsigned long long acc[16];
            #pragma unroll
            for (int ug = 0; ug < 16; ug++) acc[ug] = 0ull;

            #pragma unroll 1
            for (int jb = 0; jb < 32; jb += 8) {
                ulonglong2 hv[8];
                #pragma unroll
                for (int j = 0; j < 8; j++)
                    hv[j] = ldcg_u2(hb + (size_t)((kq0 + jb + j) * 32 + lane) * 4);
                #pragma unroll
                for (int j = 0; j < 8; j++) {
                    const ulonglong2* wq = (const ulonglong2*)(s_wz + (size_t)(kq0 + jb + j) * 64);
                    #pragma unroll
                    for (int ug = 0; ug < 16; ug++) {
                        ulonglong2 w2 = wq[ug];
                        fma2(acc[ug], hv[j].x, w2.x);
                        fma2(acc[ug], hv[j].y, w2.y);
                    }
                }
            }
            #pragma unroll
            for (int ug = 0; ug < 16; ug++) {
                float2 p = unpack2(acc[ug]);
                s_red[(wp * 16 + ug) * 32 + lane] = zacc[ug] + p.x + p.y;
            }
            __syncthreads();

            float zp = 0.f;
            if (qa) {
                float m = bm2, s = bs2;
                #pragma unroll
                for (int ww = 0; ww < 8; ww++) {
                    m += s_red[(ww * 16 + wp * 2 + 0) * 32 + lane];
                    s += s_red[(ww * 16 + wp * 2 + 1) * 32 + lane];
                }
                float lv = fmaxf(s, 0.f) + log1pf(expf(-fabsf(s)));
                float eps = noise[(size_t)(t * Bx + lane) * Zd + q];
                zp = m + expf(0.5f * lv) * eps;
                stcg_f(g_zpreT + q * 32 + lane, zp);
                out_mu[(size_t)(lane * Wt + t) * Zd + q] = m;
                out_lv[(size_t)(lane * Wt + t) * Zd + q] = lv;
            }
            __syncthreads();
            if (tid == 0) {
                arrive(&g_zaprog);
                wait_ge(&g_zaprog, (unsigned)(NZB * (t + 1)));
            }
            __syncthreads();

            if (qa) {
                const float* pnf = s_pnf + wp * 104;
                float a0 = 0.f, a1 = 0.f;
                #pragma unroll 4
                for (int z2 = 0; z2 < Zd; z2 += 2) {
                    a0 = fmaf(ldcg_f(g_zpreT + (z2 + 0) * 32 + lane), pnf[z2 + 0], a0);
                    a1 = fmaf(ldcg_f(g_zpreT + (z2 + 1) * 32 + lane), pnf[z2 + 1], a1);
                }
                float zn = zp + u0 * tanhf((a0 + a1) + bpq);
                out_z[(size_t)(lane * Wt + t) * Zd + q] = zn;
                stcg_f(g_zT + q * 32 + lane, zn);
            }
            __syncthreads();
            if (tid == 0) arrive(&g_zbprog);
        }
    }
}

// ---------------- launch ----------------
extern "C" void kernel_launch(void* const* d_in, const int* in_sizes, int n_in,
                              void* d_out, int out_size)
{
    const float* x    = (const float*)d_in[0];
    const float* Wih  = (const float*)d_in[1];
    const float* Whh  = (const float*)d_in[2];
    const float* bih  = (const float*)d_in[3];
    const float* bhh  = (const float*)d_in[4];
    const float* Wd   = (const float*)d_in[5];
    const float* bd   = (const float*)d_in[6];
    const float* Wmu  = (const float*)d_in[7];
    const float* bmu  = (const float*)d_in[8];
    const float* Wsig = (const float*)d_in[9];
    const float* bsig = (const float*)d_in[10];
    const float* u    = (const float*)d_in[11];
    const float* Wpnf = (const float*)d_in[12];
    const float* bpnf = (const float*)d_in[13];
    const float* noise= (const float*)d_in[14];
    float* out = (float*)d_out;

    cudaFuncSetAttribute(mega, cudaFuncAttributeMaxDynamicSharedMemorySize, MEGA_SMEM);

    prep_kernel<<<(Zd * ZH + 255) / 256, 256>>>(Wd, bd, Wmu, bmu, Wsig, bsig);
    conv_x<<<(8192 * 4096) / (8 * 256), 256>>>(x);
    conv_w<<<(3072 * 4096) / (8 * 256), 256>>>(Wih);
    mega<<<NCTA, 256, MEGA_SMEM>>>(Whh, bhh, u, Wpnf, bpnf, noise, bih, out);
}